// round 2
// baseline (speedup 1.0000x reference)
#include <cuda_runtime.h>
#include <cuda_bf16.h>

#define Bb   128
#define Ss   512
#define Vv   128
#define Ee   64
#define Hh   256
#define IN1  320     // E + H
#define G4   1024    // 4*H

// ---------------- device scratch (allocation-free) ----------------
__device__ __align__(16) float g_Hbuf[Bb * Ss * Hh];     // h history       [b][t][j]
__device__ __align__(16) float g_WhH [Bb * Ss * Hh];     // W_h @ h history [b][t][j]
__device__ __align__(16) float g_Wg_t[IN1 * G4];         // W_gates^T   [e][k]
__device__ __align__(16) float g_Whs_t[Hh * (2 * Hh)];   // [W_h;W_s]^T [e][j(512)]
__device__ __align__(16) float g_Wc_t[(2 * Hh) * Hh];    // W_comb^T    [e][j]
__device__ __align__(16) float g_Wo_t[Hh * Vv];          // W_out^T     [e][v]

__device__ __forceinline__ float tanha(float x) {
    float y;
    asm("tanh.approx.f32 %0, %1;" : "=f"(y) : "f"(x));
    return y;
}
__device__ __forceinline__ float sigm(float x) { return 1.f / (1.f + __expf(-x)); }

// ---------------- weight transpose prep ----------------
__global__ void prep_kernel(const float* __restrict__ Wg, const float* __restrict__ Wh,
                            const float* __restrict__ Ws, const float* __restrict__ Wc,
                            const float* __restrict__ Wo) {
    int stride = gridDim.x * blockDim.x;
    int t0 = blockIdx.x * blockDim.x + threadIdx.x;
    for (int i = t0; i < G4 * IN1; i += stride) {
        int k = i / IN1, e = i - k * IN1;
        g_Wg_t[e * G4 + k] = Wg[i];
    }
    for (int i = t0; i < Hh * Hh; i += stride) {
        int j = i / Hh, e = i - j * Hh;
        g_Whs_t[e * (2 * Hh) + j]      = Wh[i];
        g_Whs_t[e * (2 * Hh) + Hh + j] = Ws[i];
    }
    for (int i = t0; i < Hh * 2 * Hh; i += stride) {
        int j = i / (2 * Hh), e = i - j * (2 * Hh);
        g_Wc_t[e * Hh + j] = Wc[i];
    }
    for (int i = t0; i < Vv * Hh; i += stride) {
        int v = i / Hh, e = i - v * Hh;
        g_Wo_t[e * Vv + v] = Wo[i];
    }
}

// ---------------- main recurrent kernel: 2 batch rows per block ----------------
__global__ __launch_bounds__(1024, 1) void rnn_kernel(
    const int* __restrict__ x, const int* __restrict__ lengths,
    const float* __restrict__ emb, const float* __restrict__ b_gates,
    const float* __restrict__ v_attn, const float* __restrict__ b_comb,
    const float* __restrict__ b_out, float* __restrict__ out)
{
    __shared__ __align__(16) float sh_in [2][IN1];     // [emb(64), h(256)]
    __shared__ __align__(16) float sh_in2[2][2 * Hh];  // [h(256), ctx(256)]
    __shared__ __align__(16) float sh_c  [2][Hh];      // cell state
    __shared__ __align__(16) float sh_s  [2][Hh];      // W_s @ h
    __shared__ __align__(16) float sh_sc [2][Ss];      // scores -> exp weights
    __shared__ __align__(16) float sh_cb [2][Hh];      // combined
    __shared__ __align__(16) float sh_red[4 * G4];     // 16KB partial-reduce scratch
    __shared__ float sh_rw[2][32];                     // [0..15]=warp max, [16..31]=warp sum
    __shared__ int   sh_m[2];

    const int tid  = threadIdx.x;
    const int lane = tid & 31;
    const int wid  = tid >> 5;
    const int b0   = blockIdx.x * 2;

    // init state
    for (int i = tid; i < 2 * Hh; i += 1024) {
        int bh = i >> 8, j = i & 255;
        sh_c[bh][j] = 0.f;
        sh_in[bh][Ee + j] = 0.f;
    }
    if (tid < 2) sh_m[tid] = lengths[b0 + tid];

    // attention per-lane constants: lane handles dims j = lane*8 .. lane*8+7
    float vj[8];
    {
        int j0 = lane * 8;
#pragma unroll
        for (int k = 0; k < 8; k++) vj[k] = v_attn[j0 + k];
    }
    __syncthreads();

    for (int t = 0; t < Ss; t++) {
        // ---------- embedding lookup ----------
        if (tid < 2 * Ee) {
            int bh = tid >> 6, e = tid & 63;
            int tok = x[(b0 + bh) * Ss + t];
            sh_in[bh][e] = emb[tok * Ee + e];
        }
        __syncthreads();

        // ---------- gates partial: [1024] = W_gates @ [emb;h] ----------
        {
            int q = tid & 255, sub = tid >> 8;       // sub = bh + 2*eh
            int bh = sub & 1, eh = sub >> 1;
            const float4* W4 = (const float4*)g_Wg_t;
            float4 acc = make_float4(0.f, 0.f, 0.f, 0.f);
            int e = eh * 160;
#pragma unroll 4
            for (int i = 0; i < 160; i++, e++) {
                float4 w = W4[e * (G4 / 4) + q];
                float xv = sh_in[bh][e];
                acc.x = fmaf(w.x, xv, acc.x); acc.y = fmaf(w.y, xv, acc.y);
                acc.z = fmaf(w.z, xv, acc.z); acc.w = fmaf(w.w, xv, acc.w);
            }
            ((float4*)sh_red)[sub * (G4 / 4) + q] = acc;
        }
        __syncthreads();

        // ---------- LSTM elementwise ----------
        if (tid < 512) {
            int bh = tid >> 8, j = tid & 255;
            int p0 = bh * G4, p1 = (bh + 2) * G4;
            float gi = sh_red[p0 + j]          + sh_red[p1 + j]          + b_gates[j];
            float gf = sh_red[p0 + Hh + j]     + sh_red[p1 + Hh + j]     + b_gates[Hh + j];
            float gg = sh_red[p0 + 2 * Hh + j] + sh_red[p1 + 2 * Hh + j] + b_gates[2 * Hh + j];
            float go = sh_red[p0 + 3 * Hh + j] + sh_red[p1 + 3 * Hh + j] + b_gates[3 * Hh + j];
            float c = fmaf(sigm(gf), sh_c[bh][j], sigm(gi) * tanhf(gg));
            float h = sigm(go) * tanhf(c);
            sh_c[bh][j] = c;
            sh_in[bh][Ee + j] = h;
            sh_in2[bh][j] = h;
            g_Hbuf[((b0 + bh) * Ss + t) * Hh + j] = h;
        }
        __syncthreads();

        // ---------- [WhH_t ; s_t] = [W_h;W_s] @ h, partials ----------
        {
            int q = tid & 127, sub = tid >> 7;       // sub = bh + 2*ec, ec in [0,4)
            int bh = sub & 1, ec = sub >> 1;
            const float4* W4 = (const float4*)g_Whs_t;   // row e: 128 float4
            float4 acc = make_float4(0.f, 0.f, 0.f, 0.f);
            int e = ec * 64;
#pragma unroll 4
            for (int i = 0; i < 64; i++, e++) {
                float4 w = W4[e * 128 + q];
                float hv = sh_in[bh][Ee + e];
                acc.x = fmaf(w.x, hv, acc.x); acc.y = fmaf(w.y, hv, acc.y);
                acc.z = fmaf(w.z, hv, acc.z); acc.w = fmaf(w.w, hv, acc.w);
            }
            ((float4*)sh_red)[sub * 128 + q] = acc;
        }
        __syncthreads();
        {
            int bh = tid >> 9, r = tid & 511;
            float v0 = sh_red[bh * 512 + r] + sh_red[(bh + 2) * 512 + r] +
                       sh_red[(bh + 4) * 512 + r] + sh_red[(bh + 6) * 512 + r];
            if (r < Hh) g_WhH[((b0 + bh) * Ss + t) * Hh + r] = v0;
            else        sh_s[bh][r - Hh] = v0;
        }
        __syncthreads();

        // ---------- attention scores over t' < min(t, len) ----------
        {
            int bh = wid >> 4, wl = wid & 15;
            int m = min(t, sh_m[bh]);
            float sj[8];
            {
                float4 a = ((const float4*)sh_s[bh])[lane * 2];
                float4 b = ((const float4*)sh_s[bh])[lane * 2 + 1];
                sj[0] = a.x; sj[1] = a.y; sj[2] = a.z; sj[3] = a.w;
                sj[4] = b.x; sj[5] = b.y; sj[6] = b.z; sj[7] = b.w;
            }
            const float4* Wb = (const float4*)&g_WhH[(size_t)(b0 + bh) * Ss * Hh];
            for (int tp = wl; tp < m; tp += 16) {
                const float4* row = Wb + tp * 64;
                float4 a = row[lane * 2], b = row[lane * 2 + 1];
                float acc;
                acc  = vj[0] * tanha(a.x + sj[0]);
                acc += vj[1] * tanha(a.y + sj[1]);
                acc += vj[2] * tanha(a.z + sj[2]);
                acc += vj[3] * tanha(a.w + sj[3]);
                acc += vj[4] * tanha(b.x + sj[4]);
                acc += vj[5] * tanha(b.y + sj[5]);
                acc += vj[6] * tanha(b.z + sj[6]);
                acc += vj[7] * tanha(b.w + sj[7]);
#pragma unroll
                for (int o = 16; o > 0; o >>= 1) acc += __shfl_xor_sync(0xffffffffu, acc, o);
                if (lane == 0) sh_sc[bh][tp] = acc;
            }
        }
        __syncthreads();

        // ---------- softmax (unnormalized exp; 1/sum folded into ctx) ----------
        {
            int bh = tid >> 9, th = tid & 511;
            int wl = (tid >> 5) & 15;
            int m = min(t, sh_m[bh]);
            float sc = (th < m) ? sh_sc[bh][th] : -3.4e38f;
            float wm = sc;
#pragma unroll
            for (int o = 16; o > 0; o >>= 1) wm = fmaxf(wm, __shfl_xor_sync(0xffffffffu, wm, o));
            if (lane == 0) sh_rw[bh][wl] = wm;
            __syncthreads();
            float mx = sh_rw[bh][0];
#pragma unroll
            for (int k = 1; k < 16; k++) mx = fmaxf(mx, sh_rw[bh][k]);
            float ex = (th < m) ? __expf(sc - mx) : 0.f;
            sh_sc[bh][th] = ex;
            float ssum = ex;
#pragma unroll
            for (int o = 16; o > 0; o >>= 1) ssum += __shfl_xor_sync(0xffffffffu, ssum, o);
            if (lane == 0) sh_rw[bh][16 + wl] = ssum;
        }
        __syncthreads();

        // ---------- ctx partials = sum_t' w * Hbuf ----------
        {
            int bh = tid >> 9, th = tid & 511;
            int g = th >> 6, l64 = th & 63;
            int m = min(t, sh_m[bh]);
            const float4* Hb4 = (const float4*)&g_Hbuf[(size_t)(b0 + bh) * Ss * Hh];
            float4 acc = make_float4(0.f, 0.f, 0.f, 0.f);
            for (int tp = g; tp < m; tp += 8) {
                float w = sh_sc[bh][tp];
                float4 hv = Hb4[tp * 64 + l64];
                acc.x = fmaf(w, hv.x, acc.x); acc.y = fmaf(w, hv.y, acc.y);
                acc.z = fmaf(w, hv.z, acc.z); acc.w = fmaf(w, hv.w, acc.w);
            }
            ((float4*)sh_red)[(bh * 8 + g) * 64 + l64] = acc;
        }
        __syncthreads();
        if (tid < 128) {
            int bh = tid >> 6, l64 = tid & 63;
            int m = min(t, sh_m[bh]);
            float4 acc = make_float4(0.f, 0.f, 0.f, 0.f);
#pragma unroll
            for (int g = 0; g < 8; g++) {
                float4 p = ((float4*)sh_red)[(bh * 8 + g) * 64 + l64];
                acc.x += p.x; acc.y += p.y; acc.z += p.z; acc.w += p.w;
            }
            float ssum = 0.f;
#pragma unroll
            for (int k = 0; k < 16; k++) ssum += sh_rw[bh][16 + k];
            float rinv = (m > 0) ? 1.f / ssum : 0.f;
            acc.x *= rinv; acc.y *= rinv; acc.z *= rinv; acc.w *= rinv;
            ((float4*)&sh_in2[bh][Hh])[l64] = acc;
        }
        __syncthreads();

        // ---------- combined = tanh(W_comb @ [h;ctx] + b_comb), partials ----------
        {
            int q = tid & 63, sub = tid >> 6;        // sub = bh + 2*ec, ec in [0,8)
            int bh = sub & 1, ec = sub >> 1;
            const float4* W4 = (const float4*)g_Wc_t;    // row e: 64 float4
            float4 acc = make_float4(0.f, 0.f, 0.f, 0.f);
            int e = ec * 64;
#pragma unroll 4
            for (int i = 0; i < 64; i++, e++) {
                float4 w = W4[e * 64 + q];
                float xv = sh_in2[bh][e];
                acc.x = fmaf(w.x, xv, acc.x); acc.y = fmaf(w.y, xv, acc.y);
                acc.z = fmaf(w.z, xv, acc.z); acc.w = fmaf(w.w, xv, acc.w);
            }
            ((float4*)sh_red)[sub * 64 + q] = acc;
        }
        __syncthreads();
        if (tid < 512) {
            int bh = tid >> 8, j = tid & 255;
            float v0 = 0.f;
#pragma unroll
            for (int ec = 0; ec < 8; ec++) v0 += sh_red[(bh + 2 * ec) * Hh + j];
            sh_cb[bh][j] = tanhf(v0 + b_comb[j]);
        }
        __syncthreads();

        // ---------- logits = W_out @ combined + b_out, partials ----------
        {
            int q = tid & 31, sub = tid >> 5;        // sub = bh + 2*ec, ec in [0,16)
            int bh = sub & 1, ec = sub >> 1;
            const float4* W4 = (const float4*)g_Wo_t;    // row e: 32 float4
            float4 acc = make_float4(0.f, 0.f, 0.f, 0.f);
            int e = ec * 16;
#pragma unroll
            for (int i = 0; i < 16; i++, e++) {
                float4 w = W4[e * 32 + q];
                float xv = sh_cb[bh][e];
                acc.x = fmaf(w.x, xv, acc.x); acc.y = fmaf(w.y, xv, acc.y);
                acc.z = fmaf(w.z, xv, acc.z); acc.w = fmaf(w.w, xv, acc.w);
            }
            ((float4*)sh_red)[sub * 32 + q] = acc;
        }
        __syncthreads();
        if (tid < 256) {
            int bh = tid >> 7, v = tid & 127;
            float v0 = b_out[v];
#pragma unroll
            for (int ec = 0; ec < 16; ec++) v0 += sh_red[(bh + 2 * ec) * Vv + v];
            out[((size_t)(b0 + bh) * Ss + t) * Vv + v] = v0;
        }
        __syncthreads();
    }
}

extern "C" void kernel_launch(void* const* d_in, const int* in_sizes, int n_in,
                              void* d_out, int out_size) {
    const int*   x       = (const int*)  d_in[0];
    const int*   lengths = (const int*)  d_in[1];
    const float* emb     = (const float*)d_in[2];
    const float* W_gates = (const float*)d_in[3];
    const float* b_gates = (const float*)d_in[4];
    const float* W_h     = (const float*)d_in[5];
    const float* W_s     = (const float*)d_in[6];
    const float* v_attn  = (const float*)d_in[7];
    const float* W_comb  = (const float*)d_in[8];
    const float* b_comb  = (const float*)d_in[9];
    const float* W_out   = (const float*)d_in[10];
    const float* b_out   = (const float*)d_in[11];
    float* out = (float*)d_out;

    prep_kernel<<<256, 256>>>(W_gates, W_h, W_s, W_comb, W_out);
    rnn_kernel<<<Bb / 2, 1024>>>(x, lengths, emb, b_gates, v_attn, b_comb, b_out, out);
}

// round 3
// speedup vs baseline: 1.1090x; 1.1090x over previous
#include <cuda_runtime.h>

#define Bb   128
#define Ss   512
#define Vv   128
#define Ee   64
#define Hh   256
#define IN1  320     // E + H
#define G4   1024    // 4*H

// ---------------- device scratch (allocation-free) ----------------
__device__ __align__(16) float g_Hbuf[Bb * Ss * Hh];     // h history       [b][t][j]
__device__ __align__(16) float g_WhH [Bb * Ss * Hh];     // W_h @ h history [b][t][j]
__device__ __align__(16) float g_Wg_t[IN1 * G4];         // W_gates^T   [e][k]
__device__ __align__(16) float g_Whs_t[Hh * (2 * Hh)];   // [W_h;W_s]^T [e][j(512)]
__device__ __align__(16) float g_Wc_t[(2 * Hh) * Hh];    // W_comb^T    [e][j]
__device__ __align__(16) float g_Wo_t[Hh * Vv];          // W_out^T     [e][v]

__device__ __forceinline__ float tanha(float x) {
    float y;
    asm("tanh.approx.f32 %0, %1;" : "=f"(y) : "f"(x));
    return y;
}
__device__ __forceinline__ float sigm(float x) { return 1.f / (1.f + __expf(-x)); }

#define BARA() asm volatile("bar.sync 1, 512;" ::: "memory")
#define BARB() asm volatile("bar.sync 2, 512;" ::: "memory")

// ---------------- weight transpose prep ----------------
__global__ void prep_kernel(const float* __restrict__ Wg, const float* __restrict__ Wh,
                            const float* __restrict__ Ws, const float* __restrict__ Wc,
                            const float* __restrict__ Wo) {
    int stride = gridDim.x * blockDim.x;
    int t0 = blockIdx.x * blockDim.x + threadIdx.x;
    for (int i = t0; i < G4 * IN1; i += stride) {
        int k = i / IN1, e = i - k * IN1;
        g_Wg_t[e * G4 + k] = Wg[i];
    }
    for (int i = t0; i < Hh * Hh; i += stride) {
        int j = i / Hh, e = i - j * Hh;
        g_Whs_t[e * (2 * Hh) + j]      = Wh[i];
        g_Whs_t[e * (2 * Hh) + Hh + j] = Ws[i];
    }
    for (int i = t0; i < Hh * 2 * Hh; i += stride) {
        int j = i / (2 * Hh), e = i - j * (2 * Hh);
        g_Wc_t[e * Hh + j] = Wc[i];
    }
    for (int i = t0; i < Vv * Hh; i += stride) {
        int v = i / Hh, e = i - v * Hh;
        g_Wo_t[e * Vv + v] = Wo[i];
    }
}

// ---------------- main recurrent kernel ----------------
// 2 batch rows per block. Warps 0-15 (group A): LSTM recurrence at step t.
// Warps 16-31 (group B): attention + combined + logits for step t-1.
__global__ __launch_bounds__(1024, 1) void rnn_kernel(
    const int* __restrict__ x, const int* __restrict__ lengths,
    const float* __restrict__ emb, const float* __restrict__ b_gates,
    const float* __restrict__ v_attn, const float* __restrict__ b_comb,
    const float* __restrict__ b_out, float* __restrict__ out)
{
    __shared__ __align__(16) float sh_e  [2][68];         // emb (padded: bank split)
    __shared__ __align__(16) float sh_h  [2][2][264];     // slot, bh, h (padded)
    __shared__ __align__(16) float sh_s  [2][2][256];     // slot, bh, W_s@h
    __shared__ __align__(16) float sh_c  [2][256];        // cell state (A only)
    __shared__ __align__(16) float sh_scrA[2048];         // A scratch (gates out / Whs partials)
    __shared__ __align__(16) float sh_scrB[2048];         // B scratch (ctx/comb/out partials)
    __shared__ __align__(16) float sh_sc [2][512];        // scores -> exp weights
    __shared__ __align__(16) float sh_ctx[2][256];
    __shared__ __align__(16) float sh_cb [2][256];
    __shared__ float sh_mw[2][8], sh_sw[2][8];
    __shared__ int   sh_m[2];

    const int tid  = threadIdx.x;
    const int lane = tid & 31;
    const int b0   = blockIdx.x * 2;
    const bool isA = tid < 512;

    // ---- init ----
    for (int i = tid; i < 2 * 256; i += 1024) {
        int bh = i >> 8, j = i & 255;
        sh_c[bh][j] = 0.f;
        sh_h[0][bh][j] = 0.f;
        sh_h[1][bh][j] = 0.f;
    }
    if (tid < 2) sh_m[tid] = lengths[b0 + tid];

    // per-lane v_attn (used by B score warps)
    float vj[8];
    {
        const float4* v4 = (const float4*)v_attn;
        float4 a = v4[lane * 2], b = v4[lane * 2 + 1];
        vj[0] = a.x; vj[1] = a.y; vj[2] = a.z; vj[3] = a.w;
        vj[4] = b.x; vj[5] = b.y; vj[6] = b.z; vj[7] = b.w;
    }
    __syncthreads();

    for (int it = 0; it <= Ss; it++) {
        if (isA) {
            if (it < Ss) {
                const int t = it;
                const int slot = t & 1, prev = slot ^ 1;
                const int ta = tid;
                // ---- embedding ----
                if (ta < 128) {
                    int bh = ta >> 6, e = ta & 63;
                    int tok = __ldg(&x[(b0 + bh) * Ss + t]);
                    sh_e[bh][e] = __ldg(&emb[tok * Ee + e]);
                }
                BARA();
                // ---- gates: thread (bh,q) computes float4 outputs 4q..4q+3 ----
                {
                    int bh = ta & 1, q = ta >> 1;
                    const float4* W4 = (const float4*)g_Wg_t;
                    const float* hv = sh_h[prev][bh];
                    float4 acc = make_float4(0.f, 0.f, 0.f, 0.f);
#pragma unroll 8
                    for (int e = 0; e < 256; e++) {
                        float4 w = W4[(64 + e) * 256 + q];
                        float xv = hv[e];
                        acc.x = fmaf(w.x, xv, acc.x); acc.y = fmaf(w.y, xv, acc.y);
                        acc.z = fmaf(w.z, xv, acc.z); acc.w = fmaf(w.w, xv, acc.w);
                    }
#pragma unroll 8
                    for (int e = 0; e < 64; e++) {
                        float4 w = W4[e * 256 + q];
                        float xv = sh_e[bh][e];
                        acc.x = fmaf(w.x, xv, acc.x); acc.y = fmaf(w.y, xv, acc.y);
                        acc.z = fmaf(w.z, xv, acc.z); acc.w = fmaf(w.w, xv, acc.w);
                    }
                    ((float4*)sh_scrA)[bh * 256 + q] = acc;
                }
                BARA();
                // ---- LSTM elementwise ----
                {
                    int bh = ta >> 8, j = ta & 255;
                    const float* g = &sh_scrA[bh * 1024];
                    float gi = g[j]           + __ldg(&b_gates[j]);
                    float gf = g[256 + j]     + __ldg(&b_gates[256 + j]);
                    float gg = g[512 + j]     + __ldg(&b_gates[512 + j]);
                    float go = g[768 + j]     + __ldg(&b_gates[768 + j]);
                    float c = fmaf(sigm(gf), sh_c[bh][j], sigm(gi) * tanhf(gg));
                    float h = sigm(go) * tanhf(c);
                    sh_c[bh][j] = c;
                    sh_h[slot][bh][j] = h;
                    g_Hbuf[((size_t)(b0 + bh) * Ss + t) * Hh + j] = h;
                }
                BARA();
                // ---- [WhH_t ; s_t] = [W_h;W_s] @ h_t (e-split by 2) ----
                {
                    int eh = ta >> 8, r = ta & 255, bh = r >> 7, q = r & 127;
                    const float4* W4 = (const float4*)g_Whs_t;
                    const float* hv = sh_h[slot][bh];
                    float4 acc = make_float4(0.f, 0.f, 0.f, 0.f);
                    int e0 = eh * 128;
#pragma unroll 8
                    for (int i = 0; i < 128; i++) {
                        float4 w = W4[(e0 + i) * 128 + q];
                        float xv = hv[e0 + i];
                        acc.x = fmaf(w.x, xv, acc.x); acc.y = fmaf(w.y, xv, acc.y);
                        acc.z = fmaf(w.z, xv, acc.z); acc.w = fmaf(w.w, xv, acc.w);
                    }
                    ((float4*)sh_scrA)[eh * 256 + r] = acc;
                }
                BARA();
                if (ta < 256) {
                    int bh = ta >> 7, q = ta & 127;
                    float4 a = ((float4*)sh_scrA)[ta];
                    float4 b = ((float4*)sh_scrA)[256 + ta];
                    float4 v = make_float4(a.x + b.x, a.y + b.y, a.z + b.z, a.w + b.w);
                    if (q < 64)
                        ((float4*)&g_WhH[((size_t)(b0 + bh) * Ss + t) * Hh])[q] = v;
                    else
                        ((float4*)sh_s[slot][bh])[q - 64] = v;
                }
            }
        } else {
            if (it >= 1) {
                const int t = it - 1;
                const int slot = t & 1;
                const int tb = tid - 512;
                // ---- attention scores over rows < min(t, len) ----
                {
                    int bh = tb >> 8, wl = (tb >> 5) & 7;
                    int m = min(t, sh_m[bh]);
                    float sj[8];
                    {
                        float4 a = ((const float4*)sh_s[slot][bh])[lane * 2];
                        float4 b = ((const float4*)sh_s[slot][bh])[lane * 2 + 1];
                        sj[0] = a.x; sj[1] = a.y; sj[2] = a.z; sj[3] = a.w;
                        sj[4] = b.x; sj[5] = b.y; sj[6] = b.z; sj[7] = b.w;
                    }
                    const float4* Wb = (const float4*)&g_WhH[(size_t)(b0 + bh) * Ss * Hh];
#pragma unroll 2
                    for (int tp = wl; tp < m; tp += 8) {
                        float4 a = Wb[tp * 64 + lane * 2];
                        float4 b = Wb[tp * 64 + lane * 2 + 1];
                        float acc;
                        acc  = vj[0] * tanha(a.x + sj[0]);
                        acc += vj[1] * tanha(a.y + sj[1]);
                        acc += vj[2] * tanha(a.z + sj[2]);
                        acc += vj[3] * tanha(a.w + sj[3]);
                        acc += vj[4] * tanha(b.x + sj[4]);
                        acc += vj[5] * tanha(b.y + sj[5]);
                        acc += vj[6] * tanha(b.z + sj[6]);
                        acc += vj[7] * tanha(b.w + sj[7]);
#pragma unroll
                        for (int o = 16; o > 0; o >>= 1)
                            acc += __shfl_xor_sync(0xffffffffu, acc, o);
                        if (lane == 0) sh_sc[bh][tp] = acc;
                    }
                }
                BARB();
                // ---- softmax (unnormalized; 1/sum folded into ctx) ----
                {
                    int bh = tb >> 8, th = tb & 255, w8 = (tb >> 5) & 7;
                    int m = min(t, sh_m[bh]);
                    float s0 = (th < m)       ? sh_sc[bh][th]       : -3.4e38f;
                    float s1 = (th + 256 < m) ? sh_sc[bh][th + 256] : -3.4e38f;
                    float wm = fmaxf(s0, s1);
#pragma unroll
                    for (int o = 16; o > 0; o >>= 1)
                        wm = fmaxf(wm, __shfl_xor_sync(0xffffffffu, wm, o));
                    if (lane == 0) sh_mw[bh][w8] = wm;
                    BARB();
                    float mx = sh_mw[bh][0];
#pragma unroll
                    for (int k = 1; k < 8; k++) mx = fmaxf(mx, sh_mw[bh][k]);
                    float e0 = (th < m)       ? __expf(s0 - mx) : 0.f;
                    float e1 = (th + 256 < m) ? __expf(s1 - mx) : 0.f;
                    sh_sc[bh][th]       = e0;
                    sh_sc[bh][th + 256] = e1;
                    float sm = e0 + e1;
#pragma unroll
                    for (int o = 16; o > 0; o >>= 1)
                        sm += __shfl_xor_sync(0xffffffffu, sm, o);
                    if (lane == 0) sh_sw[bh][w8] = sm;
                }
                BARB();
                // ---- ctx partials ----
                {
                    int bh = tb >> 8, r = tb & 255, g = r >> 6, l = r & 63;
                    int m = min(t, sh_m[bh]);
                    const float4* Hb4 = (const float4*)&g_Hbuf[(size_t)(b0 + bh) * Ss * Hh];
                    float4 acc = make_float4(0.f, 0.f, 0.f, 0.f);
#pragma unroll 2
                    for (int tp = g; tp < m; tp += 4) {
                        float w = sh_sc[bh][tp];
                        float4 hv = Hb4[tp * 64 + l];
                        acc.x = fmaf(w, hv.x, acc.x); acc.y = fmaf(w, hv.y, acc.y);
                        acc.z = fmaf(w, hv.z, acc.z); acc.w = fmaf(w, hv.w, acc.w);
                    }
                    ((float4*)sh_scrB)[bh * 256 + g * 64 + l] = acc;
                }
                BARB();
                if (tb < 128) {
                    int bh = tb >> 6, l = tb & 63;
                    int m = min(t, sh_m[bh]);
                    float4 acc = make_float4(0.f, 0.f, 0.f, 0.f);
#pragma unroll
                    for (int g = 0; g < 4; g++) {
                        float4 p = ((float4*)sh_scrB)[bh * 256 + g * 64 + l];
                        acc.x += p.x; acc.y += p.y; acc.z += p.z; acc.w += p.w;
                    }
                    float sm = 0.f;
#pragma unroll
                    for (int k = 0; k < 8; k++) sm += sh_sw[bh][k];
                    float rinv = (m > 0) ? 1.f / sm : 0.f;
                    acc.x *= rinv; acc.y *= rinv; acc.z *= rinv; acc.w *= rinv;
                    ((float4*)sh_ctx[bh])[l] = acc;
                }
                BARB();
                // ---- combined partials: thread (bh, ec, q), e-range 128 ----
                {
                    int bh = tb >> 8, r = tb & 255, ec = r >> 6, q = r & 63;
                    const float4* W4 = (const float4*)g_Wc_t;
                    const float* xv = (ec < 2) ? &sh_h[slot][bh][ec * 128]
                                               : &sh_ctx[bh][(ec - 2) * 128];
                    float4 acc = make_float4(0.f, 0.f, 0.f, 0.f);
                    int e0 = ec * 128;
#pragma unroll 8
                    for (int i = 0; i < 128; i++) {
                        float4 w = W4[(e0 + i) * 64 + q];
                        float v = xv[i];
                        acc.x = fmaf(w.x, v, acc.x); acc.y = fmaf(w.y, v, acc.y);
                        acc.z = fmaf(w.z, v, acc.z); acc.w = fmaf(w.w, v, acc.w);
                    }
                    ((float4*)sh_scrB)[bh * 256 + ec * 64 + q] = acc;
                }
                BARB();
                if (tb < 128) {
                    int bh = tb >> 6, q = tb & 63;
                    float4 acc = ((const float4*)b_comb)[q];
#pragma unroll
                    for (int ec = 0; ec < 4; ec++) {
                        float4 p = ((float4*)sh_scrB)[bh * 256 + ec * 64 + q];
                        acc.x += p.x; acc.y += p.y; acc.z += p.z; acc.w += p.w;
                    }
                    acc.x = tanhf(acc.x); acc.y = tanhf(acc.y);
                    acc.z = tanhf(acc.z); acc.w = tanhf(acc.w);
                    ((float4*)sh_cb[bh])[q] = acc;
                }
                BARB();
                // ---- logits partials: thread (bh, ec in [0,8), q in [0,32)) ----
                {
                    int bh = tb >> 8, r = tb & 255, ec = r >> 5, q = r & 31;
                    const float4* W4 = (const float4*)g_Wo_t;
                    const float* xv = &sh_cb[bh][ec * 32];
                    float4 acc = make_float4(0.f, 0.f, 0.f, 0.f);
                    int e0 = ec * 32;
#pragma unroll 8
                    for (int i = 0; i < 32; i++) {
                        float4 w = W4[(e0 + i) * 32 + q];
                        float v = xv[i];
                        acc.x = fmaf(w.x, v, acc.x); acc.y = fmaf(w.y, v, acc.y);
                        acc.z = fmaf(w.z, v, acc.z); acc.w = fmaf(w.w, v, acc.w);
                    }
                    ((float4*)sh_scrB)[bh * 256 + ec * 32 + q] = acc;
                }
                BARB();
                if (tb < 64) {
                    int bh = tb >> 5, q = tb & 31;
                    float4 acc = ((const float4*)b_out)[q];
#pragma unroll
                    for (int ec = 0; ec < 8; ec++) {
                        float4 p = ((float4*)sh_scrB)[bh * 256 + ec * 32 + q];
                        acc.x += p.x; acc.y += p.y; acc.z += p.z; acc.w += p.w;
                    }
                    ((float4*)&out[((size_t)(b0 + bh) * Ss + t) * Vv])[q] = acc;
                }
            }
        }
        __syncthreads();   // pipeline rendezvous: A finished step it, B finished step it-1
    }
}

extern "C" void kernel_launch(void* const* d_in, const int* in_sizes, int n_in,
                              void* d_out, int out_size) {
    const int*   x       = (const int*)  d_in[0];
    const int*   lengths = (const int*)  d_in[1];
    const float* emb     = (const float*)d_in[2];
    const float* W_gates = (const float*)d_in[3];
    const float* b_gates = (const float*)d_in[4];
    const float* W_h     = (const float*)d_in[5];
    const float* W_s     = (const float*)d_in[6];
    const float* v_attn  = (const float*)d_in[7];
    const float* W_comb  = (const float*)d_in[8];
    const float* b_comb  = (const float*)d_in[9];
    const float* W_out   = (const float*)d_in[10];
    const float* b_out   = (const float*)d_in[11];
    float* out = (float*)d_out;

    prep_kernel<<<256, 256>>>(W_gates, W_h, W_s, W_comb, W_out);
    rnn_kernel<<<Bb / 2, 1024>>>(x, lengths, emb, b_gates, v_attn, b_comb, b_out, out);
}